// round 1
// baseline (speedup 1.0000x reference)
#include <cuda_runtime.h>
#include <cuda_bf16.h>
#include <math_constants.h>

// Problem constants
#define BQ   4
#define LQ   4096
#define DQ   128
#define NBQ  64            // number of 64-wide blocks along L
#define MTOT (BQ * LQ)     // 16384 rows

// ---------------------------------------------------------------------------
// Scratch (no allocations allowed -> __device__ globals)
// ---------------------------------------------------------------------------
__device__ float g_qkv[6 * MTOT * DQ];        // 6 planes [M,128]: qr,qi,kr,ki,vr,vi (50 MB)
__device__ float g_att[MTOT * 2 * DQ];        // attention output [M,256] (17 MB)
__device__ int   g_cnt[NBQ];
__device__ int   g_list[NBQ][NBQ];

// ---------------------------------------------------------------------------
// Kernel A: compact the block mask into per-qblock lists of active k-blocks.
// Mask is block-constant (64x64 repeat). Runtime dtype probe: element (0,0)
// is guaranteed True (diagonal block), which disambiguates fp32/int32/bool.
// ---------------------------------------------------------------------------
__global__ void build_mask_kernel(const void* __restrict__ mask)
{
    int qb = threadIdx.x;
    if (qb >= NBQ) return;

    const float*         mf = (const float*)mask;
    const int*           mi = (const int*)mask;
    const unsigned char* mb = (const unsigned char*)mask;

    int mode;
    if (mf[0] == 1.0f)      mode = 0;   // float32 mask
    else if (mi[0] == 1)    mode = 1;   // int32 mask
    else                    mode = 2;   // bool / uint8 bytes

    int cnt = 0;
    for (int kb = 0; kb <= qb; kb++) {
        size_t idx = (size_t)(qb * 64) * (size_t)LQ + (size_t)(kb * 64);
        bool on;
        if (mode == 0)      on = (mf[idx] != 0.0f);
        else if (mode == 1) on = (mi[idx] != 0);
        else                on = (mb[idx] != 0);
        if (on) g_list[qb][cnt++] = kb;
    }
    g_cnt[qb] = cnt;
}

// ---------------------------------------------------------------------------
// Kernel B: QKV GEMM. Y[16384,768] = X[16384,768] @ W^T + b
// X is the virtual concat of the 6 input tensors. Output scattered into the
// 6 planes of g_qkv. Tiling: 128x128x8, 256 threads, 8x8 per thread.
// ---------------------------------------------------------------------------
__global__ __launch_bounds__(256) void gemm_qkv_kernel(
    const float* __restrict__ x0, const float* __restrict__ x1,
    const float* __restrict__ x2, const float* __restrict__ x3,
    const float* __restrict__ x4, const float* __restrict__ x5,
    const float* __restrict__ W,  const float* __restrict__ bias)
{
    __shared__ __align__(16) float As[8][132];
    __shared__ __align__(16) float Bs[8][132];

    const float* xs[6] = {x0, x1, x2, x3, x4, x5};

    int tid = threadIdx.x;
    int tx  = tid & 15;
    int ty  = tid >> 4;
    int m0  = blockIdx.y * 128;
    int n0  = blockIdx.x * 128;
    int lm  = tid >> 1;           // 0..127
    int lk  = (tid & 1) * 4;      // 0 or 4

    float acc[8][8];
#pragma unroll
    for (int i = 0; i < 8; i++)
#pragma unroll
        for (int j = 0; j < 8; j++) acc[i][j] = 0.f;

    for (int k0 = 0; k0 < 768; k0 += 8) {
        int kg = k0 + lk;
        const float* xp = xs[kg >> 7];              // 8-wide k-slab never crosses a plane
        float4 a4 = *(const float4*)(xp + (size_t)(m0 + lm) * DQ + (kg & 127));
        As[lk + 0][lm] = a4.x; As[lk + 1][lm] = a4.y;
        As[lk + 2][lm] = a4.z; As[lk + 3][lm] = a4.w;

        float4 b4 = *(const float4*)(W + (size_t)(n0 + lm) * 768 + kg);
        Bs[lk + 0][lm] = b4.x; Bs[lk + 1][lm] = b4.y;
        Bs[lk + 2][lm] = b4.z; Bs[lk + 3][lm] = b4.w;

        __syncthreads();
#pragma unroll
        for (int k = 0; k < 8; k++) {
            float a[8], b[8];
            *(float4*)(a)     = *(const float4*)&As[k][ty * 8];
            *(float4*)(a + 4) = *(const float4*)&As[k][ty * 8 + 4];
            *(float4*)(b)     = *(const float4*)&Bs[k][tx * 8];
            *(float4*)(b + 4) = *(const float4*)&Bs[k][tx * 8 + 4];
#pragma unroll
            for (int i = 0; i < 8; i++)
#pragma unroll
                for (int j = 0; j < 8; j++)
                    acc[i][j] += a[i] * b[j];
        }
        __syncthreads();
    }

    // epilogue: this CTA's 128-wide n-tile is exactly one plane
    int plane = blockIdx.x;
    float* out = g_qkv + (size_t)plane * MTOT * DQ;
    float bv[8];
#pragma unroll
    for (int j = 0; j < 8; j++) bv[j] = bias[n0 + tx * 8 + j];
#pragma unroll
    for (int i = 0; i < 8; i++) {
        int row = m0 + ty * 8 + i;
        float4 v0 = make_float4(acc[i][0] + bv[0], acc[i][1] + bv[1],
                                acc[i][2] + bv[2], acc[i][3] + bv[3]);
        float4 v1 = make_float4(acc[i][4] + bv[4], acc[i][5] + bv[5],
                                acc[i][6] + bv[6], acc[i][7] + bv[7]);
        *(float4*)(out + (size_t)row * DQ + tx * 8)     = v0;
        *(float4*)(out + (size_t)row * DQ + tx * 8 + 4) = v1;
    }
}

// ---------------------------------------------------------------------------
// Kernel C: block-sparse flash attention. One CTA per (qblock, part, batch).
// 256 threads. Visits only active 64x64 K/V blocks; online softmax in fp32.
// ---------------------------------------------------------------------------
#define QS_STRIDE 132
#define SS_STRIDE 68
#define ATTN_SMEM_FLOATS (3 * 64 * QS_STRIDE + 64 * SS_STRIDE + 64 + 64)
#define ATTN_SMEM_BYTES  (ATTN_SMEM_FLOATS * 4)

__global__ __launch_bounds__(256) void attn_kernel()
{
    extern __shared__ __align__(16) float sm[];
    float* Qs     = sm;                                 // 64 x 132
    float* Ks     = sm + 64 * QS_STRIDE;                // 64 x 132
    float* Vs     = sm + 2 * 64 * QS_STRIDE;            // 64 x 132
    float* Ss     = sm + 3 * 64 * QS_STRIDE;            // 64 x 68
    float* corr_s = Ss + 64 * SS_STRIDE;                // 64
    float* l_s    = corr_s + 64;                        // 64

    int tid  = threadIdx.x;
    int qb   = blockIdx.x;
    int part = blockIdx.y;
    int b    = blockIdx.z;

    const float* Qp = g_qkv + (size_t)(0 + part) * MTOT * DQ;
    const float* Kp = g_qkv + (size_t)(2 + part) * MTOT * DQ;
    const float* Vp = g_qkv + (size_t)(4 + part) * MTOT * DQ;

    int qrow0 = b * LQ + qb * 64;
    const float scale = 0.08838834764831845f;   // 1/sqrt(128)

    // load Q tile, pre-scaled
#pragma unroll
    for (int it = 0; it < 8; it++) {
        int e  = tid + it * 256;        // float4 index, 0..2047
        int r  = e >> 5;
        int c4 = (e & 31) * 4;
        float4 v = *(const float4*)(Qp + (size_t)(qrow0 + r) * DQ + c4);
        v.x *= scale; v.y *= scale; v.z *= scale; v.w *= scale;
        *(float4*)(Qs + r * QS_STRIDE + c4) = v;
    }

    // role mappings
    int q_s   = tid >> 2;      // softmax: one query per 4-thread group
    int lane4 = tid & 3;
    int qy    = tid >> 4;      // PV/S: 4 query rows  (qy*4 ..)
    int dx    = tid & 15;      // PV: 8 d-cols (dx*8 ..) / S: 4 k rows (dx*4 ..)

    float m_run = -CUDART_INF_F;
    float l_run = 0.f;
    float O[4][8];
#pragma unroll
    for (int a = 0; a < 4; a++)
#pragma unroll
        for (int j = 0; j < 8; j++) O[a][j] = 0.f;

    int cnt = g_cnt[qb];
    for (int i = 0; i < cnt; i++) {
        int kb    = g_list[qb][i];
        int krow0 = b * LQ + kb * 64;

        // load K and V tiles
#pragma unroll
        for (int it = 0; it < 8; it++) {
            int e  = tid + it * 256;
            int r  = e >> 5;
            int c4 = (e & 31) * 4;
            *(float4*)(Ks + r * QS_STRIDE + c4) =
                *(const float4*)(Kp + (size_t)(krow0 + r) * DQ + c4);
            *(float4*)(Vs + r * QS_STRIDE + c4) =
                *(const float4*)(Vp + (size_t)(krow0 + r) * DQ + c4);
        }
        __syncthreads();

        // S = (Q*scale) @ K^T : each thread computes a 4x4 subtile
        float s4[4][4];
#pragma unroll
        for (int a = 0; a < 4; a++)
#pragma unroll
            for (int c = 0; c < 4; c++) s4[a][c] = 0.f;

        for (int d = 0; d < 128; d++) {
            float qa[4], kk[4];
#pragma unroll
            for (int a = 0; a < 4; a++) qa[a] = Qs[(qy * 4 + a) * QS_STRIDE + d];
#pragma unroll
            for (int c = 0; c < 4; c++) kk[c] = Ks[(dx * 4 + c) * QS_STRIDE + d];
#pragma unroll
            for (int a = 0; a < 4; a++)
#pragma unroll
                for (int c = 0; c < 4; c++)
                    s4[a][c] += qa[a] * kk[c];
        }
#pragma unroll
        for (int a = 0; a < 4; a++)
#pragma unroll
            for (int c = 0; c < 4; c++)
                Ss[(qy * 4 + a) * SS_STRIDE + dx * 4 + c] = s4[a][c];
        __syncthreads();

        // online softmax (4 threads per query row, 16 cols each)
        float* srow = Ss + q_s * SS_STRIDE + lane4 * 16;
        float pv[16];
        float mx = -CUDART_INF_F;
#pragma unroll
        for (int t = 0; t < 16; t++) { pv[t] = srow[t]; mx = fmaxf(mx, pv[t]); }
        mx = fmaxf(mx, __shfl_xor_sync(0xffffffffu, mx, 1, 4));
        mx = fmaxf(mx, __shfl_xor_sync(0xffffffffu, mx, 2, 4));
        float m_new = fmaxf(m_run, mx);
        float dm    = m_run - m_new;
        float corr  = (dm < -80.f) ? 0.f : __expf(dm);
        float psum  = 0.f;
#pragma unroll
        for (int t = 0; t < 16; t++) {
            float e = pv[t] - m_new;
            float p = (e < -80.f) ? 0.f : __expf(e);
            srow[t] = p;
            psum += p;
        }
        psum += __shfl_xor_sync(0xffffffffu, psum, 1, 4);
        psum += __shfl_xor_sync(0xffffffffu, psum, 2, 4);
        l_run = l_run * corr + psum;
        m_run = m_new;
        if (lane4 == 0) corr_s[q_s] = corr;
        __syncthreads();

        // O = O*corr + P @ V : each thread owns a 4x8 output subtile
        float cf[4];
#pragma unroll
        for (int a = 0; a < 4; a++) cf[a] = corr_s[qy * 4 + a];
#pragma unroll
        for (int a = 0; a < 4; a++)
#pragma unroll
            for (int j = 0; j < 8; j++) O[a][j] *= cf[a];

        for (int k = 0; k < 64; k++) {
            float p[4];
#pragma unroll
            for (int a = 0; a < 4; a++) p[a] = Ss[(qy * 4 + a) * SS_STRIDE + k];
            float v8[8];
            *(float4*)(v8)     = *(const float4*)(Vs + k * QS_STRIDE + dx * 8);
            *(float4*)(v8 + 4) = *(const float4*)(Vs + k * QS_STRIDE + dx * 8 + 4);
#pragma unroll
            for (int a = 0; a < 4; a++)
#pragma unroll
                for (int j = 0; j < 8; j++)
                    O[a][j] += p[a] * v8[j];
        }
        __syncthreads();
    }

    if (lane4 == 0) l_s[q_s] = l_run;
    __syncthreads();

#pragma unroll
    for (int a = 0; a < 4; a++) {
        float inv = 1.f / l_s[qy * 4 + a];
        int   row = qrow0 + qy * 4 + a;
        float4 v0 = make_float4(O[a][0] * inv, O[a][1] * inv, O[a][2] * inv, O[a][3] * inv);
        float4 v1 = make_float4(O[a][4] * inv, O[a][5] * inv, O[a][6] * inv, O[a][7] * inv);
        size_t off = (size_t)row * (2 * DQ) + part * DQ + dx * 8;
        *(float4*)(g_att + off)     = v0;
        *(float4*)(g_att + off + 4) = v1;
    }
}

// ---------------------------------------------------------------------------
// Kernel D: output projection. out[16384,256] = g_att @ W_out^T + b_out,
// split into the two 128-wide halves of d_out ([out0 flat][out1 flat]).
// ---------------------------------------------------------------------------
__global__ __launch_bounds__(256) void gemm_out_kernel(
    const float* __restrict__ W, const float* __restrict__ bias,
    float* __restrict__ dout)
{
    __shared__ __align__(16) float As[8][132];
    __shared__ __align__(16) float Bs[8][132];

    int tid = threadIdx.x;
    int tx  = tid & 15;
    int ty  = tid >> 4;
    int m0  = blockIdx.y * 128;
    int n0  = blockIdx.x * 128;
    int lm  = tid >> 1;
    int lk  = (tid & 1) * 4;

    float acc[8][8];
#pragma unroll
    for (int i = 0; i < 8; i++)
#pragma unroll
        for (int j = 0; j < 8; j++) acc[i][j] = 0.f;

    for (int k0 = 0; k0 < 256; k0 += 8) {
        int kg = k0 + lk;
        float4 a4 = *(const float4*)(g_att + (size_t)(m0 + lm) * 256 + kg);
        As[lk + 0][lm] = a4.x; As[lk + 1][lm] = a4.y;
        As[lk + 2][lm] = a4.z; As[lk + 3][lm] = a4.w;

        float4 b4 = *(const float4*)(W + (size_t)(n0 + lm) * 256 + kg);
        Bs[lk + 0][lm] = b4.x; Bs[lk + 1][lm] = b4.y;
        Bs[lk + 2][lm] = b4.z; Bs[lk + 3][lm] = b4.w;

        __syncthreads();
#pragma unroll
        for (int k = 0; k < 8; k++) {
            float a[8], b[8];
            *(float4*)(a)     = *(const float4*)&As[k][ty * 8];
            *(float4*)(a + 4) = *(const float4*)&As[k][ty * 8 + 4];
            *(float4*)(b)     = *(const float4*)&Bs[k][tx * 8];
            *(float4*)(b + 4) = *(const float4*)&Bs[k][tx * 8 + 4];
#pragma unroll
            for (int i = 0; i < 8; i++)
#pragma unroll
                for (int j = 0; j < 8; j++)
                    acc[i][j] += a[i] * b[j];
        }
        __syncthreads();
    }

    // epilogue: part 0 -> d_out[0 : M*128), part 1 -> d_out[M*128 : 2*M*128)
    int part = blockIdx.x;
    float* out = dout + (size_t)part * MTOT * DQ;
    float bv[8];
#pragma unroll
    for (int j = 0; j < 8; j++) bv[j] = bias[n0 + tx * 8 + j];
#pragma unroll
    for (int i = 0; i < 8; i++) {
        int row = m0 + ty * 8 + i;
        float4 v0 = make_float4(acc[i][0] + bv[0], acc[i][1] + bv[1],
                                acc[i][2] + bv[2], acc[i][3] + bv[3]);
        float4 v1 = make_float4(acc[i][4] + bv[4], acc[i][5] + bv[5],
                                acc[i][6] + bv[6], acc[i][7] + bv[7]);
        *(float4*)(out + (size_t)row * DQ + tx * 8)     = v0;
        *(float4*)(out + (size_t)row * DQ + tx * 8 + 4) = v1;
    }
}

// ---------------------------------------------------------------------------
// Launch
// ---------------------------------------------------------------------------
extern "C" void kernel_launch(void* const* d_in, const int* in_sizes, int n_in,
                              void* d_out, int out_size)
{
    const float* q_real = (const float*)d_in[0];
    const float* q_imag = (const float*)d_in[1];
    const float* k_real = (const float*)d_in[2];
    const float* k_imag = (const float*)d_in[3];
    const float* v_real = (const float*)d_in[4];
    const float* v_imag = (const float*)d_in[5];
    const float* W_qkv  = (const float*)d_in[6];
    const float* b_qkv  = (const float*)d_in[7];
    const float* W_out  = (const float*)d_in[8];
    const float* b_out  = (const float*)d_in[9];
    const void*  mask   = d_in[10];
    float* out = (float*)d_out;

    (void)in_sizes; (void)n_in; (void)out_size;

    // idempotent; safe during capture (not a stream op)
    cudaFuncSetAttribute(attn_kernel, cudaFuncAttributeMaxDynamicSharedMemorySize,
                         ATTN_SMEM_BYTES);

    build_mask_kernel<<<1, 64>>>(mask);
    gemm_qkv_kernel<<<dim3(6, 128), 256>>>(q_real, q_imag, k_real, k_imag,
                                           v_real, v_imag, W_qkv, b_qkv);
    attn_kernel<<<dim3(NBQ, 2, BQ), 256, ATTN_SMEM_BYTES>>>();
    gemm_out_kernel<<<dim3(2, 128), 256>>>(W_out, b_out, out);
}

// round 3
// speedup vs baseline: 1.4519x; 1.4519x over previous
#include <cuda_runtime.h>
#include <cuda_bf16.h>
#include <math_constants.h>
#include <cstdint>

// Problem constants
#define BQ   4
#define LQ   4096
#define DQ   128
#define NBQ  64
#define MTOT (BQ * LQ)     // 16384 rows

// ---------------------------------------------------------------------------
// Scratch (__device__ globals; no allocations allowed)
// ---------------------------------------------------------------------------
__device__ float g_qkv[6 * MTOT * DQ];              // fp32 planes qr,qi,kr,ki,vr,vi
__device__ float g_att[MTOT * 2 * DQ];              // attention out [M,256] fp32
__device__ __nv_bfloat16 g_Xh[6 * MTOT * DQ];       // input hi/lo split (plane-major)
__device__ __nv_bfloat16 g_Xl[6 * MTOT * DQ];
__device__ __nv_bfloat16 g_Wqh[768 * 768];
__device__ __nv_bfloat16 g_Wql[768 * 768];
__device__ __nv_bfloat16 g_Ath[MTOT * 256];
__device__ __nv_bfloat16 g_Atl[MTOT * 256];
__device__ __nv_bfloat16 g_Woh[256 * 256];
__device__ __nv_bfloat16 g_Wol[256 * 256];
__device__ int   g_cnt[NBQ];
__device__ int   g_list[NBQ][NBQ];

// ---------------------------------------------------------------------------
// Helpers
// ---------------------------------------------------------------------------
__device__ __forceinline__ uint32_t smem_to_u32(const void* p) {
    uint32_t a;
    asm("{ .reg .u64 t; cvta.to.shared.u64 t, %1; cvt.u32.u64 %0, t; }" : "=r"(a) : "l"(p));
    return a;
}
__device__ __forceinline__ void cp16(uint32_t dst_smem, const void* src) {
    asm volatile("cp.async.cg.shared.global [%0], [%1], 16;" :: "r"(dst_smem), "l"(src));
}
#define CP_COMMIT() asm volatile("cp.async.commit_group;" ::: "memory")
#define CP_WAIT(n)  asm volatile("cp.async.wait_group %0;" :: "n"(n) : "memory")

__device__ __forceinline__ void ldmx4(uint32_t* r, uint32_t addr) {
    asm volatile("ldmatrix.sync.aligned.m8n8.x4.shared.b16 {%0,%1,%2,%3}, [%4];"
                 : "=r"(r[0]), "=r"(r[1]), "=r"(r[2]), "=r"(r[3]) : "r"(addr));
}
__device__ __forceinline__ void ldmx2(uint32_t* r, uint32_t addr) {
    asm volatile("ldmatrix.sync.aligned.m8n8.x2.shared.b16 {%0,%1}, [%2];"
                 : "=r"(r[0]), "=r"(r[1]) : "r"(addr));
}
__device__ __forceinline__ void mma_bf16(float* c, const uint32_t* a, const uint32_t* b) {
    asm volatile(
        "mma.sync.aligned.m16n8k16.row.col.f32.bf16.bf16.f32 "
        "{%0,%1,%2,%3}, {%4,%5,%6,%7}, {%8,%9}, {%0,%1,%2,%3};"
        : "+f"(c[0]), "+f"(c[1]), "+f"(c[2]), "+f"(c[3])
        : "r"(a[0]), "r"(a[1]), "r"(a[2]), "r"(a[3]), "r"(b[0]), "r"(b[1]));
}

// ---------------------------------------------------------------------------
// Kernel: fp32 -> bf16 hi/lo split (error-free 2-term decomposition)
// ---------------------------------------------------------------------------
__global__ void split_kernel(const float4* __restrict__ src,
                             uint2* __restrict__ hi, uint2* __restrict__ lo, int n4)
{
    int i = blockIdx.x * 256 + threadIdx.x;
    if (i >= n4) return;
    float4 v = src[i];
    float f[4] = {v.x, v.y, v.z, v.w};
    uint32_t hw[4], lw[4];
#pragma unroll
    for (int j = 0; j < 4; j++) {
        __nv_bfloat16 h = __float2bfloat16(f[j]);
        __nv_bfloat16 l = __float2bfloat16(f[j] - __bfloat162float(h));
        hw[j] = (uint32_t)__bfloat16_as_ushort(h);
        lw[j] = (uint32_t)__bfloat16_as_ushort(l);
    }
    hi[i] = make_uint2((hw[1] << 16) | hw[0], (hw[3] << 16) | hw[2]);
    lo[i] = make_uint2((lw[1] << 16) | lw[0], (lw[3] << 16) | lw[2]);
}

// ---------------------------------------------------------------------------
// Kernel: block-mask compaction (dtype probe; (0,0) is guaranteed True)
// ---------------------------------------------------------------------------
__global__ void build_mask_kernel(const void* __restrict__ mask)
{
    int qb = threadIdx.x;
    if (qb >= NBQ) return;
    const float* mf = (const float*)mask;
    const int*   mi = (const int*)mask;
    const unsigned char* mb = (const unsigned char*)mask;
    int mode;
    if (mf[0] == 1.0f)   mode = 0;
    else if (mi[0] == 1) mode = 1;
    else                 mode = 2;
    int cnt = 0;
    for (int kb = 0; kb <= qb; kb++) {
        size_t idx = (size_t)(qb * 64) * (size_t)LQ + (size_t)(kb * 64);
        bool on;
        if (mode == 0)      on = (mf[idx] != 0.0f);
        else if (mode == 1) on = (mi[idx] != 0);
        else                on = (mb[idx] != 0);
        if (on) g_list[qb][cnt++] = kb;
    }
    g_cnt[qb] = cnt;
}

// ---------------------------------------------------------------------------
// HMMA GEMM: C[M,N] = A @ B^T + bias, A,B split into bf16 hi/lo.
// D += Ah*Bh + Ah*Bl + Al*Bh   (fp32-accurate to ~2^-17)
// Tile 128x128x32, 256 threads (8 warps as 2Mx4N, 64x32 warp tiles),
// cp.async double buffer, stride-40 smem rows (conflict-free ldmatrix).
// MODE 0: QKV (K=768, A plane-major, C -> g_qkv planes, gridDim.x=6)
// MODE 1: OUT (K=256, A row-major [M,256], C -> d_out halves, gridDim.x=2)
// ---------------------------------------------------------------------------
#define GSTRIDE 40                      // smem row stride in bf16 elems (80B)
#define MATE    (128 * GSTRIDE)         // elems per matrix tile (5120)
#define MATB    (MATE * 2)              // bytes per matrix tile (10240)
#define STAGEB  (4 * MATB)              // bytes per stage (Ah,Al,Bh,Bl) 40960
#define GEMM_SMEM (2 * STAGEB)          // 81920

template<int MODE>
__global__ __launch_bounds__(256, 1) void gemm_mma_impl(
    const __nv_bfloat16* __restrict__ Ah, const __nv_bfloat16* __restrict__ Al,
    const __nv_bfloat16* __restrict__ Bh, const __nv_bfloat16* __restrict__ Bl,
    const float* __restrict__ bias, float* __restrict__ Cout)
{
    constexpr int KTOT = (MODE == 0) ? 768 : 256;
    constexpr int NCH  = KTOT / 32;

    extern __shared__ __align__(128) char smc[];
    uint32_t sbase0 = smem_to_u32(smc);

    int tid  = threadIdx.x;
    int warp = tid >> 5, lane = tid & 31;
    int wm = warp & 1;
    int wn = warp >> 1;
    int m0 = blockIdx.y * 128;
    int n0 = blockIdx.x * 128;

    auto load_stage = [&](int ch, int buf) {
        int k0 = ch * 32;
        uint32_t sb = sbase0 + buf * STAGEB;
#pragma unroll
        for (int i = 0; i < 2; i++) {
            int e = tid + i * 256;
            int r = e >> 2, seg = e & 3;
            uint32_t off = (uint32_t)(r * GSTRIDE + seg * 8) * 2;
            size_t ga;
            if (MODE == 0) ga = ((size_t)(k0 >> 7) * MTOT + m0 + r) * 128 + (k0 & 127) + seg * 8;
            else           ga = (size_t)(m0 + r) * KTOT + k0 + seg * 8;
            cp16(sb + off,            Ah + ga);
            cp16(sb + MATB + off,     Al + ga);
            size_t gb = (size_t)(n0 + r) * KTOT + k0 + seg * 8;
            cp16(sb + 2 * MATB + off, Bh + gb);
            cp16(sb + 3 * MATB + off, Bl + gb);
        }
    };

    float acc[4][4][4];
#pragma unroll
    for (int mf = 0; mf < 4; mf++)
#pragma unroll
        for (int nf = 0; nf < 4; nf++)
#pragma unroll
            for (int j = 0; j < 4; j++) acc[mf][nf][j] = 0.f;

    load_stage(0, 0); CP_COMMIT();
    load_stage(1, 1); CP_COMMIT();
    CP_WAIT(1);
    __syncthreads();

    int li = lane & 15;
    uint32_t a_row_off = (uint32_t)((wm * 64 + li) * GSTRIDE) * 2;
    uint32_t a_col_off = (uint32_t)((lane >> 4) * 8) * 2;
    uint32_t b_row_off = (uint32_t)((wn * 32 + (li & 7)) * GSTRIDE) * 2;
    uint32_t b_col_off = (uint32_t)((li >> 3) * 8) * 2;

    for (int ch = 0; ch < NCH; ch++) {
        uint32_t sb = sbase0 + (ch & 1) * STAGEB;
#pragma unroll
        for (int k16 = 0; k16 < 2; k16++) {
            uint32_t kofs = (uint32_t)(k16 * 16) * 2;
            uint32_t ah[4][4], al[4][4];
#pragma unroll
            for (int mf = 0; mf < 4; mf++) {
                uint32_t addr = sb + a_row_off
                              + (uint32_t)(mf * 16 * GSTRIDE * 2) + kofs + a_col_off;
                ldmx4(ah[mf], addr);
                ldmx4(al[mf], addr + MATB);
            }
            uint32_t bh[4][2], bl[4][2];
#pragma unroll
            for (int nf = 0; nf < 4; nf++) {
                uint32_t addr = sb + 2 * MATB + b_row_off
                              + (uint32_t)(nf * 8 * GSTRIDE * 2) + kofs + b_col_off;
                ldmx2(bh[nf], addr);
                ldmx2(bl[nf], addr + MATB);
            }
#pragma unroll
            for (int mf = 0; mf < 4; mf++)
#pragma unroll
                for (int nf = 0; nf < 4; nf++) {
                    mma_bf16(acc[mf][nf], ah[mf], bh[nf]);
                    mma_bf16(acc[mf][nf], ah[mf], bl[nf]);
                    mma_bf16(acc[mf][nf], al[mf], bh[nf]);
                }
        }
        __syncthreads();
        if (ch + 2 < NCH) { load_stage(ch + 2, ch & 1); CP_COMMIT(); }
        if (ch + 1 < NCH) {
            if (ch + 2 < NCH) { CP_WAIT(1); } else { CP_WAIT(0); }
            __syncthreads();
        }
    }

    // epilogue: C frag m16n8 layout — c0,c1 at row lane/4, c2,c3 at row+8
#pragma unroll
    for (int mf = 0; mf < 4; mf++) {
        int r0 = m0 + wm * 64 + mf * 16 + (lane >> 2);
#pragma unroll
        for (int nf = 0; nf < 4; nf++) {
            int cp = wn * 32 + nf * 8 + (lane & 3) * 2;
            float b0 = __ldg(bias + blockIdx.x * 128 + cp);
            float b1 = __ldg(bias + blockIdx.x * 128 + cp + 1);
            float* dst;
            if (MODE == 0) dst = g_qkv + (size_t)blockIdx.x * MTOT * 128;
            else           dst = Cout  + (size_t)blockIdx.x * MTOT * 128;
            float2 v01 = make_float2(acc[mf][nf][0] + b0, acc[mf][nf][1] + b1);
            float2 v23 = make_float2(acc[mf][nf][2] + b0, acc[mf][nf][3] + b1);
            *(float2*)(dst + (size_t)r0 * 128 + cp)       = v01;
            *(float2*)(dst + (size_t)(r0 + 8) * 128 + cp) = v23;
        }
    }
}

// ---------------------------------------------------------------------------
// Block-sparse flash attention (fp32) — unchanged from passing R1 kernel.
// ---------------------------------------------------------------------------
#define QS_STRIDE 132
#define SS_STRIDE 68
#define ATTN_SMEM_FLOATS (3 * 64 * QS_STRIDE + 64 * SS_STRIDE + 64 + 64)
#define ATTN_SMEM_BYTES  (ATTN_SMEM_FLOATS * 4)

__global__ __launch_bounds__(256) void attn_kernel()
{
    extern __shared__ __align__(16) float smf[];
    float* Qs     = smf;
    float* Ks     = smf + 64 * QS_STRIDE;
    float* Vs     = smf + 2 * 64 * QS_STRIDE;
    float* Ss     = smf + 3 * 64 * QS_STRIDE;
    float* corr_s = Ss + 64 * SS_STRIDE;
    float* l_s    = corr_s + 64;

    int tid  = threadIdx.x;
    int qb   = blockIdx.x;
    int part = blockIdx.y;
    int b    = blockIdx.z;

    const float* Qp = g_qkv + (size_t)(0 + part) * MTOT * DQ;
    const float* Kp = g_qkv + (size_t)(2 + part) * MTOT * DQ;
    const float* Vp = g_qkv + (size_t)(4 + part) * MTOT * DQ;

    int qrow0 = b * LQ + qb * 64;
    const float scale = 0.08838834764831845f;

#pragma unroll
    for (int it = 0; it < 8; it++) {
        int e  = tid + it * 256;
        int r  = e >> 5;
        int c4 = (e & 31) * 4;
        float4 v = *(const float4*)(Qp + (size_t)(qrow0 + r) * DQ + c4);
        v.x *= scale; v.y *= scale; v.z *= scale; v.w *= scale;
        *(float4*)(Qs + r * QS_STRIDE + c4) = v;
    }

    int q_s   = tid >> 2;
    int lane4 = tid & 3;
    int qy    = tid >> 4;
    int dx    = tid & 15;

    float m_run = -CUDART_INF_F;
    float l_run = 0.f;
    float O[4][8];
#pragma unroll
    for (int a = 0; a < 4; a++)
#pragma unroll
        for (int j = 0; j < 8; j++) O[a][j] = 0.f;

    int cnt = g_cnt[qb];
    for (int i = 0; i < cnt; i++) {
        int kb    = g_list[qb][i];
        int krow0 = b * LQ + kb * 64;

#pragma unroll
        for (int it = 0; it < 8; it++) {
            int e  = tid + it * 256;
            int r  = e >> 5;
            int c4 = (e & 31) * 4;
            *(float4*)(Ks + r * QS_STRIDE + c4) =
                *(const float4*)(Kp + (size_t)(krow0 + r) * DQ + c4);
            *(float4*)(Vs + r * QS_STRIDE + c4) =
                *(const float4*)(Vp + (size_t)(krow0 + r) * DQ + c4);
        }
        __syncthreads();

        float s4[4][4];
#pragma unroll
        for (int a = 0; a < 4; a++)
#pragma unroll
            for (int c = 0; c < 4; c++) s4[a][c] = 0.f;

        for (int d = 0; d < 128; d++) {
            float qa[4], kk[4];
#pragma unroll
            for (int a = 0; a < 4; a++) qa[a] = Qs[(qy * 4 + a) * QS_STRIDE + d];
#pragma unroll
            for (int c = 0; c < 4; c++) kk[c] = Ks[(dx * 4 + c) * QS_STRIDE + d];
#pragma unroll
            for (int a = 0; a < 4; a++)
#pragma unroll
                for (int c = 0; c < 4; c++)
                    s4[a][c] += qa[a] * kk[c];
        }
#pragma unroll
        for (int a = 0; a < 4; a++)
#pragma unroll
            for (int c = 0; c < 4; c++)
                Ss[(qy * 4 + a) * SS_STRIDE + dx * 4 + c] = s4[a][c];
        __syncthreads();

        float* srow = Ss + q_s * SS_STRIDE + lane4 * 16;
        float pv[16];
        float mx = -CUDART_INF_F;
#pragma unroll
        for (int t = 0; t < 16; t++) { pv[t] = srow[t]; mx = fmaxf(mx, pv[t]); }
        mx = fmaxf(mx, __shfl_xor_sync(0xffffffffu, mx, 1, 4));
        mx = fmaxf(mx, __shfl_xor_sync(0xffffffffu, mx, 2, 4));
        float m_new = fmaxf(m_run, mx);
        float dm    = m_run - m_new;
        float corr  = (dm < -80.f) ? 0.f : __expf(dm);
        float psum  = 0.f;
#pragma unroll
        for (int t = 0; t < 16; t++) {
            float e = pv[t] - m_new;
            float p = (e < -80.f) ? 0.f : __expf(e);
            srow[t] = p;
            psum += p;
        }
        psum += __shfl_xor_sync(0xffffffffu, psum, 1, 4);
        psum += __shfl_xor_sync(0xffffffffu, psum, 2, 4);
        l_run = l_run * corr + psum;
        m_run = m_new;
        if (lane4 == 0) corr_s[q_s] = corr;
        __syncthreads();

        float cf[4];
#pragma unroll
        for (int a = 0; a < 4; a++) cf[a] = corr_s[qy * 4 + a];
#pragma unroll
        for (int a = 0; a < 4; a++)
#pragma unroll
            for (int j = 0; j < 8; j++) O[a][j] *= cf[a];

        for (int k = 0; k < 64; k++) {
            float p[4];
#pragma unroll
            for (int a = 0; a < 4; a++) p[a] = Ss[(qy * 4 + a) * SS_STRIDE + k];
            float v8[8];
            *(float4*)(v8)     = *(const float4*)(Vs + k * QS_STRIDE + dx * 8);
            *(float4*)(v8 + 4) = *(const float4*)(Vs + k * QS_STRIDE + dx * 8 + 4);
#pragma unroll
            for (int a = 0; a < 4; a++)
#pragma unroll
                for (int j = 0; j < 8; j++)
                    O[a][j] += p[a] * v8[j];
        }
        __syncthreads();
    }

    if (lane4 == 0) l_s[q_s] = l_run;
    __syncthreads();

#pragma unroll
    for (int a = 0; a < 4; a++) {
        float inv = 1.f / l_s[qy * 4 + a];
        int   row = qrow0 + qy * 4 + a;
        float4 v0 = make_float4(O[a][0] * inv, O[a][1] * inv, O[a][2] * inv, O[a][3] * inv);
        float4 v1 = make_float4(O[a][4] * inv, O[a][5] * inv, O[a][6] * inv, O[a][7] * inv);
        size_t off = (size_t)row * (2 * DQ) + part * DQ + dx * 8;
        *(float4*)(g_att + off)     = v0;
        *(float4*)(g_att + off + 4) = v1;
    }
}

// ---------------------------------------------------------------------------
// Launch
// ---------------------------------------------------------------------------
extern "C" void kernel_launch(void* const* d_in, const int* in_sizes, int n_in,
                              void* d_out, int out_size)
{
    const float* xin[6];
    for (int i = 0; i < 6; i++) xin[i] = (const float*)d_in[i];
    const float* W_qkv  = (const float*)d_in[6];
    const float* b_qkv  = (const float*)d_in[7];
    const float* W_out  = (const float*)d_in[8];
    const float* b_out  = (const float*)d_in[9];
    const void*  mask   = d_in[10];
    float* out = (float*)d_out;
    (void)in_sizes; (void)n_in; (void)out_size;

    cudaFuncSetAttribute(attn_kernel, cudaFuncAttributeMaxDynamicSharedMemorySize,
                         ATTN_SMEM_BYTES);
    cudaFuncSetAttribute(gemm_mma_impl<0>, cudaFuncAttributeMaxDynamicSharedMemorySize,
                         GEMM_SMEM);
    cudaFuncSetAttribute(gemm_mma_impl<1>, cudaFuncAttributeMaxDynamicSharedMemorySize,
                         GEMM_SMEM);

    __nv_bfloat16 *Xh, *Xl, *Wqh, *Wql, *Ath, *Atl, *Woh, *Wol;
    float *att;
    cudaGetSymbolAddress((void**)&Xh,  g_Xh);
    cudaGetSymbolAddress((void**)&Xl,  g_Xl);
    cudaGetSymbolAddress((void**)&Wqh, g_Wqh);
    cudaGetSymbolAddress((void**)&Wql, g_Wql);
    cudaGetSymbolAddress((void**)&Ath, g_Ath);
    cudaGetSymbolAddress((void**)&Atl, g_Atl);
    cudaGetSymbolAddress((void**)&Woh, g_Woh);
    cudaGetSymbolAddress((void**)&Wol, g_Wol);
    cudaGetSymbolAddress((void**)&att, g_att);

    build_mask_kernel<<<1, 64>>>(mask);

    const int PLANE4 = MTOT * DQ / 4;
    for (int i = 0; i < 6; i++)
        split_kernel<<<(PLANE4 + 255) / 256, 256>>>((const float4*)xin[i],
            (uint2*)(Xh + (size_t)i * MTOT * DQ), (uint2*)(Xl + (size_t)i * MTOT * DQ), PLANE4);
    split_kernel<<<(768 * 768 / 4 + 255) / 256, 256>>>((const float4*)W_qkv,
        (uint2*)Wqh, (uint2*)Wql, 768 * 768 / 4);
    split_kernel<<<(256 * 256 / 4 + 255) / 256, 256>>>((const float4*)W_out,
        (uint2*)Woh, (uint2*)Wol, 256 * 256 / 4);

    gemm_mma_impl<0><<<dim3(6, MTOT / 128), 256, GEMM_SMEM>>>(
        Xh, Xl, Wqh, Wql, b_qkv, nullptr);

    attn_kernel<<<dim3(NBQ, 2, BQ), 256, ATTN_SMEM_BYTES>>>();

    split_kernel<<<(MTOT * 256 / 4 + 255) / 256, 256>>>((const float4*)att,
        (uint2*)Ath, (uint2*)Atl, MTOT * 256 / 4);
    gemm_mma_impl<1><<<dim3(2, MTOT / 128), 256, GEMM_SMEM>>>(
        Ath, Atl, Woh, Wol, b_out, out);
}

// round 5
// speedup vs baseline: 2.5402x; 1.7496x over previous
#include <cuda_runtime.h>
#include <cuda_bf16.h>
#include <math_constants.h>
#include <cstdint>

// Problem constants
#define BQ   4
#define LQ   4096
#define DQ   128
#define NBQ  64
#define MTOT (BQ * LQ)     // 16384 rows

// ---------------------------------------------------------------------------
// Scratch (__device__ globals; no allocations allowed)
// ---------------------------------------------------------------------------
__device__ float g_att[MTOT * 2 * DQ];              // attention out [M,256] fp32
__device__ __nv_bfloat16 g_Xh[6 * MTOT * DQ];       // input hi/lo split (plane-major)
__device__ __nv_bfloat16 g_Xl[6 * MTOT * DQ];
__device__ __nv_bfloat16 g_Wqh[768 * 768];
__device__ __nv_bfloat16 g_Wql[768 * 768];
__device__ __nv_bfloat16 g_QKVh[6 * MTOT * DQ];     // QKV projection out, hi/lo
__device__ __nv_bfloat16 g_QKVl[6 * MTOT * DQ];
__device__ __nv_bfloat16 g_Ath[MTOT * 256];
__device__ __nv_bfloat16 g_Atl[MTOT * 256];
__device__ __nv_bfloat16 g_Woh[256 * 256];
__device__ __nv_bfloat16 g_Wol[256 * 256];
__device__ int   g_cnt[NBQ];
__device__ int   g_list[NBQ][NBQ];

// ---------------------------------------------------------------------------
// Helpers
// ---------------------------------------------------------------------------
__device__ __forceinline__ uint32_t smem_to_u32(const void* p) {
    uint32_t a;
    asm("{ .reg .u64 t; cvta.to.shared.u64 t, %1; cvt.u32.u64 %0, t; }" : "=r"(a) : "l"(p));
    return a;
}
__device__ __forceinline__ void cp16(uint32_t dst_smem, const void* src) {
    asm volatile("cp.async.cg.shared.global [%0], [%1], 16;" :: "r"(dst_smem), "l"(src));
}
#define CP_COMMIT() asm volatile("cp.async.commit_group;" ::: "memory")
#define CP_WAIT(n)  asm volatile("cp.async.wait_group %0;" :: "n"(n) : "memory")

__device__ __forceinline__ void ldmx4(uint32_t* r, uint32_t addr) {
    asm volatile("ldmatrix.sync.aligned.m8n8.x4.shared.b16 {%0,%1,%2,%3}, [%4];"
                 : "=r"(r[0]), "=r"(r[1]), "=r"(r[2]), "=r"(r[3]) : "r"(addr));
}
__device__ __forceinline__ void ldmx4t(uint32_t* r, uint32_t addr) {
    asm volatile("ldmatrix.sync.aligned.m8n8.x4.trans.shared.b16 {%0,%1,%2,%3}, [%4];"
                 : "=r"(r[0]), "=r"(r[1]), "=r"(r[2]), "=r"(r[3]) : "r"(addr));
}
__device__ __forceinline__ void ldmx2(uint32_t* r, uint32_t addr) {
    asm volatile("ldmatrix.sync.aligned.m8n8.x2.shared.b16 {%0,%1}, [%2];"
                 : "=r"(r[0]), "=r"(r[1]) : "r"(addr));
}
__device__ __forceinline__ void mma_bf16(float* c, const uint32_t* a,
                                         uint32_t b0, uint32_t b1) {
    asm volatile(
        "mma.sync.aligned.m16n8k16.row.col.f32.bf16.bf16.f32 "
        "{%0,%1,%2,%3}, {%4,%5,%6,%7}, {%8,%9}, {%0,%1,%2,%3};"
        : "+f"(c[0]), "+f"(c[1]), "+f"(c[2]), "+f"(c[3])
        : "r"(a[0]), "r"(a[1]), "r"(a[2]), "r"(a[3]), "r"(b0), "r"(b1));
}
__device__ __forceinline__ uint32_t pack_bf2(float a, float b) {
    __nv_bfloat162 t = __floats2bfloat162_rn(a, b);
    return *(uint32_t*)&t;
}

// ---------------------------------------------------------------------------
// fp32 -> bf16 hi/lo split
// ---------------------------------------------------------------------------
__global__ void split_kernel(const float4* __restrict__ src,
                             uint2* __restrict__ hi, uint2* __restrict__ lo, int n4)
{
    int i = blockIdx.x * 256 + threadIdx.x;
    if (i >= n4) return;
    float4 v = src[i];
    float f[4] = {v.x, v.y, v.z, v.w};
    uint32_t hw[4], lw[4];
#pragma unroll
    for (int j = 0; j < 4; j++) {
        __nv_bfloat16 h = __float2bfloat16(f[j]);
        __nv_bfloat16 l = __float2bfloat16(f[j] - __bfloat162float(h));
        hw[j] = (uint32_t)__bfloat16_as_ushort(h);
        lw[j] = (uint32_t)__bfloat16_as_ushort(l);
    }
    hi[i] = make_uint2((hw[1] << 16) | hw[0], (hw[3] << 16) | hw[2]);
    lo[i] = make_uint2((lw[1] << 16) | lw[0], (lw[3] << 16) | lw[2]);
}

// ---------------------------------------------------------------------------
// Block-mask compaction
// ---------------------------------------------------------------------------
__global__ void build_mask_kernel(const void* __restrict__ mask)
{
    int qb = threadIdx.x;
    if (qb >= NBQ) return;
    const float* mf = (const float*)mask;
    const int*   mi = (const int*)mask;
    const unsigned char* mb = (const unsigned char*)mask;
    int mode;
    if (mf[0] == 1.0f)   mode = 0;
    else if (mi[0] == 1) mode = 1;
    else                 mode = 2;
    int cnt = 0;
    for (int kb = 0; kb <= qb; kb++) {
        size_t idx = (size_t)(qb * 64) * (size_t)LQ + (size_t)(kb * 64);
        bool on;
        if (mode == 0)      on = (mf[idx] != 0.0f);
        else if (mode == 1) on = (mi[idx] != 0);
        else                on = (mb[idx] != 0);
        if (on) g_list[qb][cnt++] = kb;
    }
    g_cnt[qb] = cnt;
}

// ---------------------------------------------------------------------------
// HMMA GEMM (3-term bf16 hi/lo split). Tile 128x128x32, 8 warps.
// MODE 0: QKV (K=768) -> writes bf16 hi/lo planes g_QKVh/g_QKVl
// MODE 1: OUT (K=256) -> writes fp32 halves of d_out
// ---------------------------------------------------------------------------
#define GSTRIDE 40
#define MATE    (128 * GSTRIDE)
#define MATB    (MATE * 2)
#define STAGEB  (4 * MATB)
#define GEMM_SMEM (2 * STAGEB)

template<int MODE>
__global__ __launch_bounds__(256, 1) void gemm_mma_impl(
    const __nv_bfloat16* __restrict__ Ah, const __nv_bfloat16* __restrict__ Al,
    const __nv_bfloat16* __restrict__ Bh, const __nv_bfloat16* __restrict__ Bl,
    const float* __restrict__ bias, float* __restrict__ Cout)
{
    constexpr int KTOT = (MODE == 0) ? 768 : 256;
    constexpr int NCH  = KTOT / 32;

    extern __shared__ __align__(128) char smc[];
    uint32_t sbase0 = smem_to_u32(smc);

    int tid  = threadIdx.x;
    int warp = tid >> 5, lane = tid & 31;
    int wm = warp & 1;
    int wn = warp >> 1;
    int m0 = blockIdx.y * 128;
    int n0 = blockIdx.x * 128;

    auto load_stage = [&](int ch, int buf) {
        int k0 = ch * 32;
        uint32_t sb = sbase0 + buf * STAGEB;
#pragma unroll
        for (int i = 0; i < 2; i++) {
            int e = tid + i * 256;
            int r = e >> 2, seg = e & 3;
            uint32_t off = (uint32_t)(r * GSTRIDE + seg * 8) * 2;
            size_t ga;
            if (MODE == 0) ga = ((size_t)(k0 >> 7) * MTOT + m0 + r) * 128 + (k0 & 127) + seg * 8;
            else           ga = (size_t)(m0 + r) * KTOT + k0 + seg * 8;
            cp16(sb + off,            Ah + ga);
            cp16(sb + MATB + off,     Al + ga);
            size_t gb = (size_t)(n0 + r) * KTOT + k0 + seg * 8;
            cp16(sb + 2 * MATB + off, Bh + gb);
            cp16(sb + 3 * MATB + off, Bl + gb);
        }
    };

    float acc[4][4][4];
#pragma unroll
    for (int mf = 0; mf < 4; mf++)
#pragma unroll
        for (int nf = 0; nf < 4; nf++)
#pragma unroll
            for (int j = 0; j < 4; j++) acc[mf][nf][j] = 0.f;

    load_stage(0, 0); CP_COMMIT();
    load_stage(1, 1); CP_COMMIT();
    CP_WAIT(1);
    __syncthreads();

    int li = lane & 15;
    uint32_t a_row_off = (uint32_t)((wm * 64 + li) * GSTRIDE) * 2;
    uint32_t a_col_off = (uint32_t)((lane >> 4) * 8) * 2;
    uint32_t b_row_off = (uint32_t)((wn * 32 + (li & 7)) * GSTRIDE) * 2;
    uint32_t b_col_off = (uint32_t)((li >> 3) * 8) * 2;

    for (int ch = 0; ch < NCH; ch++) {
        uint32_t sb = sbase0 + (ch & 1) * STAGEB;
#pragma unroll
        for (int k16 = 0; k16 < 2; k16++) {
            uint32_t kofs = (uint32_t)(k16 * 16) * 2;
            uint32_t ah[4][4], al[4][4];
#pragma unroll
            for (int mf = 0; mf < 4; mf++) {
                uint32_t addr = sb + a_row_off
                              + (uint32_t)(mf * 16 * GSTRIDE * 2) + kofs + a_col_off;
                ldmx4(ah[mf], addr);
                ldmx4(al[mf], addr + MATB);
            }
            uint32_t bh[4][2], bl[4][2];
#pragma unroll
            for (int nf = 0; nf < 4; nf++) {
                uint32_t addr = sb + 2 * MATB + b_row_off
                              + (uint32_t)(nf * 8 * GSTRIDE * 2) + kofs + b_col_off;
                ldmx2(bh[nf], addr);
                ldmx2(bl[nf], addr + MATB);
            }
#pragma unroll
            for (int mf = 0; mf < 4; mf++)
#pragma unroll
                for (int nf = 0; nf < 4; nf++) {
                    mma_bf16(acc[mf][nf], ah[mf], bh[nf][0], bh[nf][1]);
                    mma_bf16(acc[mf][nf], ah[mf], bl[nf][0], bl[nf][1]);
                    mma_bf16(acc[mf][nf], al[mf], bh[nf][0], bh[nf][1]);
                }
        }
        __syncthreads();
        if (ch + 2 < NCH) { load_stage(ch + 2, ch & 1); CP_COMMIT(); }
        if (ch + 1 < NCH) {
            if (ch + 2 < NCH) { CP_WAIT(1); } else { CP_WAIT(0); }
            __syncthreads();
        }
    }

    // epilogue
#pragma unroll
    for (int mf = 0; mf < 4; mf++) {
        int r0 = m0 + wm * 64 + mf * 16 + (lane >> 2);
#pragma unroll
        for (int nf = 0; nf < 4; nf++) {
            int cp = wn * 32 + nf * 8 + (lane & 3) * 2;
            float b0 = __ldg(bias + blockIdx.x * 128 + cp);
            float b1 = __ldg(bias + blockIdx.x * 128 + cp + 1);
            float v00 = acc[mf][nf][0] + b0, v01 = acc[mf][nf][1] + b1;
            float v10 = acc[mf][nf][2] + b0, v11 = acc[mf][nf][3] + b1;
            if (MODE == 0) {
                size_t base = (size_t)blockIdx.x * MTOT * 128;
                __nv_bfloat16 h00 = __float2bfloat16(v00);
                __nv_bfloat16 h01 = __float2bfloat16(v01);
                __nv_bfloat16 h10 = __float2bfloat16(v10);
                __nv_bfloat16 h11 = __float2bfloat16(v11);
                uint32_t w0h = ((uint32_t)__bfloat16_as_ushort(h01) << 16) | __bfloat16_as_ushort(h00);
                uint32_t w1h = ((uint32_t)__bfloat16_as_ushort(h11) << 16) | __bfloat16_as_ushort(h10);
                uint32_t w0l = pack_bf2(v00 - __bfloat162float(h00), v01 - __bfloat162float(h01));
                uint32_t w1l = pack_bf2(v10 - __bfloat162float(h10), v11 - __bfloat162float(h11));
                *(uint32_t*)(g_QKVh + base + (size_t)r0 * 128 + cp)       = w0h;
                *(uint32_t*)(g_QKVl + base + (size_t)r0 * 128 + cp)       = w0l;
                *(uint32_t*)(g_QKVh + base + (size_t)(r0 + 8) * 128 + cp) = w1h;
                *(uint32_t*)(g_QKVl + base + (size_t)(r0 + 8) * 128 + cp) = w1l;
            } else {
                float* dst = Cout + (size_t)blockIdx.x * MTOT * 128;
                *(float2*)(dst + (size_t)r0 * 128 + cp)       = make_float2(v00, v01);
                *(float2*)(dst + (size_t)(r0 + 8) * 128 + cp) = make_float2(v10, v11);
            }
        }
    }
}

// ---------------------------------------------------------------------------
// HMMA block-sparse flash attention.
// CTA = (qblock, part, batch), 128 threads (4 warps x 16 query rows).
// S = Q@K^T and O = P@V both 3-term bf16 hi/lo. K/V double-buffered cp.async.
// smem rows: stride 136 elems (272B = 17*16B -> conflict-free ldmatrix).
// Each 64x128 bf16 matrix = 64 rows x 16 chunks of 16B = 1024 chunks.
// ---------------------------------------------------------------------------
#define AST   136
#define AMAT  (64 * AST)            // elems per matrix
#define AMATB (AMAT * 2)            // 17408 bytes
#define ATT_SMEM ((2 + 8) * AMATB)  // Q h/l + 2 stages * (Kh,Kl,Vh,Vl) = 174080

__global__ __launch_bounds__(128, 1) void attn_mma()
{
    extern __shared__ __align__(128) char sma[];
    uint32_t sb = smem_to_u32(sma);

    int tid  = threadIdx.x;
    int warp = tid >> 5, lane = tid & 31;
    int qb   = blockIdx.x;
    int part = blockIdx.y;
    int b    = blockIdx.z;

    const __nv_bfloat16* Qh = g_QKVh + (size_t)(0 + part) * MTOT * 128;
    const __nv_bfloat16* Ql = g_QKVl + (size_t)(0 + part) * MTOT * 128;
    const __nv_bfloat16* Kh = g_QKVh + (size_t)(2 + part) * MTOT * 128;
    const __nv_bfloat16* Kl = g_QKVl + (size_t)(2 + part) * MTOT * 128;
    const __nv_bfloat16* Vh = g_QKVh + (size_t)(4 + part) * MTOT * 128;
    const __nv_bfloat16* Vl = g_QKVl + (size_t)(4 + part) * MTOT * 128;

    int qrow0 = b * LQ + qb * 64;
    const float SC = 0.08838834764831845f * 1.4426950408889634f;  // scale * log2(e)

    // ---- loaders (FIXED: 1024 16B-chunks per 64x128 matrix) ----
    auto load_q = [&]() {
#pragma unroll
        for (int i = 0; i < 16; i++) {
            int e = tid + i * 128;            // 0..2047
            int mat = e >> 10;                // 0=h, 1=l
            int idx = e & 1023;
            int r = idx >> 4, c = idx & 15;   // 16 chunks per 128-elem row
            const __nv_bfloat16* src = (mat ? Ql : Qh) + (size_t)(qrow0 + r) * 128 + c * 8;
            cp16(sb + (uint32_t)(mat * AMATB) + (uint32_t)(r * AST + c * 8) * 2, src);
        }
    };
    auto load_kv = [&](int kb, int s) {
        int krow0 = b * LQ + kb * 64;
        uint32_t stb = sb + (uint32_t)((2 + 4 * s) * AMATB);
#pragma unroll
        for (int i = 0; i < 32; i++) {
            int e = tid + i * 128;            // 0..4095
            int mat = e >> 10;                // 0=Kh 1=Kl 2=Vh 3=Vl
            int idx = e & 1023;
            int r = idx >> 4, c = idx & 15;
            const __nv_bfloat16* src;
            if (mat == 0) src = Kh; else if (mat == 1) src = Kl;
            else if (mat == 2) src = Vh; else src = Vl;
            src += (size_t)(krow0 + r) * 128 + c * 8;
            cp16(stb + (uint32_t)(mat * AMATB) + (uint32_t)(r * AST + c * 8) * 2, src);
        }
    };

    float O[16][4];
#pragma unroll
    for (int nf = 0; nf < 16; nf++)
#pragma unroll
        for (int j = 0; j < 4; j++) O[nf][j] = 0.f;
    float m2_0 = -1e30f, m2_1 = -1e30f;
    float l0 = 0.f, l1 = 0.f;

    int cnt = g_cnt[qb];
    load_q(); load_kv(g_list[qb][0], 0); CP_COMMIT();
    if (cnt > 1) { load_kv(g_list[qb][1], 1); CP_COMMIT(); }
    if (cnt > 1) { CP_WAIT(1); } else { CP_WAIT(0); }
    __syncthreads();

    int li = lane & 15;
    uint32_t a_off = (uint32_t)((warp * 16 + li) * AST + (lane >> 4) * 8) * 2;
    uint32_t kv_row = (uint32_t)(li * AST + (lane >> 4) * 8) * 2;

    for (int i = 0; i < cnt; i++) {
        int s = i & 1;
        uint32_t sK = sb + (uint32_t)((2 + 4 * s) * AMATB);
        uint32_t sV = sK + 2 * AMATB;

        // ---- S = Q @ K^T (3-term) ----
        float sv[8][4];
#pragma unroll
        for (int nf = 0; nf < 8; nf++)
#pragma unroll
            for (int j = 0; j < 4; j++) sv[nf][j] = 0.f;

#pragma unroll
        for (int kd = 0; kd < 8; kd++) {
            uint32_t qaddr = sb + a_off + (uint32_t)(kd * 16) * 2;
            uint32_t aH[4], aL[4];
            ldmx4(aH, qaddr);
            ldmx4(aL, qaddr + AMATB);
#pragma unroll
            for (int jg = 0; jg < 4; jg++) {
                uint32_t kaddr = sK + kv_row
                               + (uint32_t)(jg * 16 * AST + kd * 16) * 2;
                uint32_t bH[4], bL[4];
                ldmx4(bH, kaddr);
                ldmx4(bL, kaddr + AMATB);
                mma_bf16(sv[jg * 2],     aH, bH[0], bH[2]);
                mma_bf16(sv[jg * 2],     aH, bL[0], bL[2]);
                mma_bf16(sv[jg * 2],     aL, bH[0], bH[2]);
                mma_bf16(sv[jg * 2 + 1], aH, bH[1], bH[3]);
                mma_bf16(sv[jg * 2 + 1], aH, bL[1], bL[3]);
                mma_bf16(sv[jg * 2 + 1], aL, bH[1], bH[3]);
            }
        }

        // ---- online softmax (log2 domain) ----
        float mx0 = -1e30f, mx1 = -1e30f;
#pragma unroll
        for (int nf = 0; nf < 8; nf++) {
#pragma unroll
            for (int j = 0; j < 4; j++) sv[nf][j] *= SC;
            mx0 = fmaxf(mx0, fmaxf(sv[nf][0], sv[nf][1]));
            mx1 = fmaxf(mx1, fmaxf(sv[nf][2], sv[nf][3]));
        }
        mx0 = fmaxf(mx0, __shfl_xor_sync(0xffffffffu, mx0, 1));
        mx0 = fmaxf(mx0, __shfl_xor_sync(0xffffffffu, mx0, 2));
        mx1 = fmaxf(mx1, __shfl_xor_sync(0xffffffffu, mx1, 1));
        mx1 = fmaxf(mx1, __shfl_xor_sync(0xffffffffu, mx1, 2));

        float m0n = fmaxf(m2_0, mx0);
        float m1n = fmaxf(m2_1, mx1);
        float cor0 = exp2f(m2_0 - m0n);
        float cor1 = exp2f(m2_1 - m1n);
        m2_0 = m0n; m2_1 = m1n;

        uint32_t ph[8][2], pl[8][2];
        float ls0 = 0.f, ls1 = 0.f;
#pragma unroll
        for (int nf = 0; nf < 8; nf++) {
            float p0 = exp2f(sv[nf][0] - m0n);
            float p1 = exp2f(sv[nf][1] - m0n);
            float p2 = exp2f(sv[nf][2] - m1n);
            float p3 = exp2f(sv[nf][3] - m1n);
            ls0 += p0 + p1; ls1 += p2 + p3;
            __nv_bfloat16 h0 = __float2bfloat16(p0), h1 = __float2bfloat16(p1);
            __nv_bfloat16 h2 = __float2bfloat16(p2), h3 = __float2bfloat16(p3);
            ph[nf][0] = ((uint32_t)__bfloat16_as_ushort(h1) << 16) | __bfloat16_as_ushort(h0);
            ph[nf][1] = ((uint32_t)__bfloat16_as_ushort(h3) << 16) | __bfloat16_as_ushort(h2);
            pl[nf][0] = pack_bf2(p0 - __bfloat162float(h0), p1 - __bfloat162float(h1));
            pl[nf][1] = pack_bf2(p2 - __bfloat162float(h2), p3 - __bfloat162float(h3));
        }
        ls0 += __shfl_xor_sync(0xffffffffu, ls0, 1);
        ls0 += __shfl_xor_sync(0xffffffffu, ls0, 2);
        ls1 += __shfl_xor_sync(0xffffffffu, ls1, 1);
        ls1 += __shfl_xor_sync(0xffffffffu, ls1, 2);
        l0 = l0 * cor0 + ls0;
        l1 = l1 * cor1 + ls1;

        // ---- rescale O ----
#pragma unroll
        for (int nf = 0; nf < 16; nf++) {
            O[nf][0] *= cor0; O[nf][1] *= cor0;
            O[nf][2] *= cor1; O[nf][3] *= cor1;
        }

        // ---- O += P @ V (3-term) ----
#pragma unroll
        for (int kk = 0; kk < 4; kk++) {
            uint32_t aH[4] = {ph[2*kk][0], ph[2*kk][1], ph[2*kk+1][0], ph[2*kk+1][1]};
            uint32_t aL[4] = {pl[2*kk][0], pl[2*kk][1], pl[2*kk+1][0], pl[2*kk+1][1]};
#pragma unroll
            for (int dg = 0; dg < 8; dg++) {
                uint32_t vaddr = sV + kv_row
                               + (uint32_t)(kk * 16 * AST + dg * 16) * 2;
                uint32_t vH[4], vL[4];
                ldmx4t(vH, vaddr);
                ldmx4t(vL, vaddr + AMATB);
                mma_bf16(O[dg * 2],     aH, vH[0], vH[1]);
                mma_bf16(O[dg * 2],     aH, vL[0], vL[1]);
                mma_bf16(O[dg * 2],     aL, vH[0], vH[1]);
                mma_bf16(O[dg * 2 + 1], aH, vH[2], vH[3]);
                mma_bf16(O[dg * 2 + 1], aH, vL[2], vL[3]);
                mma_bf16(O[dg * 2 + 1], aL, vH[2], vH[3]);
            }
        }

        __syncthreads();
        if (i + 2 < cnt) { load_kv(g_list[qb][i + 2], s); CP_COMMIT(); }
        if (i + 1 < cnt) {
            if (i + 2 < cnt) { CP_WAIT(1); } else { CP_WAIT(0); }
            __syncthreads();
        }
    }

    // ---- epilogue ----
    float inv0 = 1.f / l0, inv1 = 1.f / l1;
    int r0 = qrow0 + warp * 16 + (lane >> 2);
    int r1 = r0 + 8;
#pragma unroll
    for (int nf = 0; nf < 16; nf++) {
        int col = part * 128 + nf * 8 + (lane & 3) * 2;
        *(float2*)(g_att + (size_t)r0 * 256 + col) =
            make_float2(O[nf][0] * inv0, O[nf][1] * inv0);
        *(float2*)(g_att + (size_t)r1 * 256 + col) =
            make_float2(O[nf][2] * inv1, O[nf][3] * inv1);
    }
}

// ---------------------------------------------------------------------------
// Launch
// ---------------------------------------------------------------------------
extern "C" void kernel_launch(void* const* d_in, const int* in_sizes, int n_in,
                              void* d_out, int out_size)
{
    const float* xin[6];
    for (int i = 0; i < 6; i++) xin[i] = (const float*)d_in[i];
    const float* W_qkv  = (const float*)d_in[6];
    const float* b_qkv  = (const float*)d_in[7];
    const float* W_out  = (const float*)d_in[8];
    const float* b_out  = (const float*)d_in[9];
    const void*  mask   = d_in[10];
    float* out = (float*)d_out;
    (void)in_sizes; (void)n_in; (void)out_size;

    cudaFuncSetAttribute(attn_mma, cudaFuncAttributeMaxDynamicSharedMemorySize,
                         ATT_SMEM);
    cudaFuncSetAttribute(gemm_mma_impl<0>, cudaFuncAttributeMaxDynamicSharedMemorySize,
                         GEMM_SMEM);
    cudaFuncSetAttribute(gemm_mma_impl<1>, cudaFuncAttributeMaxDynamicSharedMemorySize,
                         GEMM_SMEM);

    __nv_bfloat16 *Xh, *Xl, *Wqh, *Wql, *Ath, *Atl, *Woh, *Wol;
    float *att;
    cudaGetSymbolAddress((void**)&Xh,  g_Xh);
    cudaGetSymbolAddress((void**)&Xl,  g_Xl);
    cudaGetSymbolAddress((void**)&Wqh, g_Wqh);
    cudaGetSymbolAddress((void**)&Wql, g_Wql);
    cudaGetSymbolAddress((void**)&Ath, g_Ath);
    cudaGetSymbolAddress((void**)&Atl, g_Atl);
    cudaGetSymbolAddress((void**)&Woh, g_Woh);
    cudaGetSymbolAddress((void**)&Wol, g_Wol);
    cudaGetSymbolAddress((void**)&att, g_att);

    build_mask_kernel<<<1, 64>>>(mask);

    const int PLANE4 = MTOT * DQ / 4;
    for (int i = 0; i < 6; i++)
        split_kernel<<<(PLANE4 + 255) / 256, 256>>>((const float4*)xin[i],
            (uint2*)(Xh + (size_t)i * MTOT * DQ), (uint2*)(Xl + (size_t)i * MTOT * DQ), PLANE4);
    split_kernel<<<(768 * 768 / 4 + 255) / 256, 256>>>((const float4*)W_qkv,
        (uint2*)Wqh, (uint2*)Wql, 768 * 768 / 4);
    split_kernel<<<(256 * 256 / 4 + 255) / 256, 256>>>((const float4*)W_out,
        (uint2*)Woh, (uint2*)Wol, 256 * 256 / 4);

    gemm_mma_impl<0><<<dim3(6, MTOT / 128), 256, GEMM_SMEM>>>(
        Xh, Xl, Wqh, Wql, b_qkv, nullptr);

    attn_mma<<<dim3(NBQ, 2, BQ), 128, ATT_SMEM>>>();

    split_kernel<<<(MTOT * 256 / 4 + 255) / 256, 256>>>((const float4*)att,
        (uint2*)Ath, (uint2*)Atl, MTOT * 256 / 4);
    gemm_mma_impl<1><<<dim3(2, MTOT / 128), 256, GEMM_SMEM>>>(
        Ath, Atl, Woh, Wol, b_out, out);
}